// round 10
// baseline (speedup 1.0000x reference)
#include <cuda_runtime.h>
#include <cuda_fp16.h>

#define D 16
#define GBLK 64

// Scratch (allocation-free rule: __device__ globals). uint4-typed for 16B alignment.
__device__ float g_MW[4096];              // MW[j][k][l] = sum_n Wc1[j,n] * M[n,k,l]
__device__ float g_bb[16];                // bb[j] = bc1[j] + sum_n Wc1[j,n]*Boff[n]
__device__ float g_E3f[20000 * 16];       // fp32 MLP output per gene (input to k_uw)
__device__ uint4 g_E3h[20000 * 2];        // fp16 MLP output per gene (input to k_main)
__device__ uint4 g_UWh[20000 * 32];       // fp16: uint4 at [g*32 + h*16 + j] = UW[g][j][8h..8h+7]

// ---- packed f32x2 helpers (sm_103a FFMA2 path; exact fp32 per lane) ----
__device__ __forceinline__ unsigned long long pk2(float a, float b) {
    unsigned long long r;
    asm("mov.b64 %0, {%1, %2};" : "=l"(r) : "f"(a), "f"(b));
    return r;
}
__device__ __forceinline__ unsigned long long fma2(unsigned long long a,
                                                   unsigned long long b,
                                                   unsigned long long c) {
    unsigned long long d;
    asm("fma.rn.f32x2 %0, %1, %2, %3;" : "=l"(d) : "l"(a), "l"(b), "l"(c));
    return d;
}
__device__ __forceinline__ float2 upk2(unsigned long long v) {
    float2 f;
    asm("mov.b64 {%0, %1}, %2;" : "=f"(f.x), "=f"(f.y) : "l"(v));
    return f;
}

// ---------------------------------------------------------------------------
// Kernel 1 (fused): blocks 0..15 compute MW[j]+bb; blocks 16.. run gene MLP
// with one thread per gene, FFMA2-packed (2 outputs per instruction).
// ---------------------------------------------------------------------------
__global__ void k_pre(const float* __restrict__ BW, const float* __restrict__ BD,
                      const float* __restrict__ Wc1, const float* __restrict__ bc1,
                      const float* __restrict__ Boff,
                      const float* __restrict__ emb,
                      const float* __restrict__ W1, const float* __restrict__ b1,
                      const float* __restrict__ W2, const float* __restrict__ b2,
                      const float* __restrict__ W3, const float* __restrict__ b3,
                      int genes) {
    int t = threadIdx.x;

    if (blockIdx.x < 16) {
        __shared__ float sBW[4096], sBD[256], sWc1[256];
        {
            const float4* s = (const float4*)BW;
            float4* d = (float4*)sBW;
#pragma unroll
            for (int q = 0; q < 4; q++) d[t + 256 * q] = s[t + 256 * q];
            if (t < 64)       ((float4*)sBD)[t]       = ((const float4*)BD)[t];
            else if (t < 128) ((float4*)sWc1)[t - 64] = ((const float4*)Wc1)[t - 64];
        }
        __syncthreads();

        int j = blockIdx.x;
        int k = t >> 4, l = t & 15;
        float s = 0.f;
#pragma unroll
        for (int n = 0; n < 16; n++) {
            float wjn = sWc1[j * 16 + n];
#pragma unroll
            for (int m = 0; m < 16; m++) {
                float p = wjn * sBD[n * 16 + m];
                s = fmaf(p * sBW[n * 256 + m * 16 + k], sBW[m * 256 + n * 16 + l], s);
            }
        }
        g_MW[j * 256 + t] = s;

        if (blockIdx.x == 0 && t < 16) {
            float b = bc1[t];
#pragma unroll
            for (int n = 0; n < 16; n++) b = fmaf(sWc1[t * 16 + n], Boff[n], b);
            g_bb[t] = b;
        }
        return;
    }

    // ---- E3 blocks: packed weights. sWp[jj*8+p] = (W[2p][jj], W[2p+1][jj]) ----
    __shared__ unsigned long long sW1p[128], sW2p[128], sW3p[128], sbp[24];
    {
        if (t < 128) {
            int jj = t >> 3, p = t & 7;
            sW1p[t] = pk2(W1[(2 * p) * 16 + jj], W1[(2 * p + 1) * 16 + jj]);
        } else {
            int tt = t - 128;
            int jj = tt >> 3, p = tt & 7;
            sW2p[tt] = pk2(W2[(2 * p) * 16 + jj], W2[(2 * p + 1) * 16 + jj]);
        }
        if (t < 128) {
            int jj = t >> 3, p = t & 7;
            sW3p[t] = pk2(W3[(2 * p) * 16 + jj], W3[(2 * p + 1) * 16 + jj]);
        } else if (t < 152) {
            int tt = t - 128;          // 0..23 : layer L = tt>>3, pair p = tt&7
            int L = tt >> 3, p = tt & 7;
            const float* bsrc = (L == 0) ? b1 : (L == 1) ? b2 : b3;
            sbp[tt] = pk2(bsrc[2 * p], bsrc[2 * p + 1]);
        }
    }
    __syncthreads();

    int g = (blockIdx.x - 16) * 256 + t;
    if (g >= genes) return;

    float v[16];
    {
        const float4* ep = (const float4*)(emb + (size_t)g * 16);
        float4 a = ep[0], b = ep[1], c = ep[2], dd = ep[3];
        v[0]=a.x; v[1]=a.y; v[2]=a.z; v[3]=a.w;
        v[4]=b.x; v[5]=b.y; v[6]=b.z; v[7]=b.w;
        v[8]=c.x; v[9]=c.y; v[10]=c.z; v[11]=c.w;
        v[12]=dd.x; v[13]=dd.y; v[14]=dd.z; v[15]=dd.w;
    }

    unsigned long long acc[8];
    // ---- layer 1 ----
#pragma unroll
    for (int p = 0; p < 8; p++) acc[p] = sbp[p];
#pragma unroll
    for (int jj = 0; jj < 16; jj++) {
        unsigned long long bv = pk2(v[jj], v[jj]);
#pragma unroll
        for (int p = 0; p < 8; p++) acc[p] = fma2(sW1p[jj * 8 + p], bv, acc[p]);
    }
#pragma unroll
    for (int p = 0; p < 8; p++) {
        float2 f = upk2(acc[p]);
        v[2 * p] = fmaxf(f.x, 0.f);
        v[2 * p + 1] = fmaxf(f.y, 0.f);
    }
    // ---- layer 2 ----
#pragma unroll
    for (int p = 0; p < 8; p++) acc[p] = sbp[8 + p];
#pragma unroll
    for (int jj = 0; jj < 16; jj++) {
        unsigned long long bv = pk2(v[jj], v[jj]);
#pragma unroll
        for (int p = 0; p < 8; p++) acc[p] = fma2(sW2p[jj * 8 + p], bv, acc[p]);
    }
#pragma unroll
    for (int p = 0; p < 8; p++) {
        float2 f = upk2(acc[p]);
        v[2 * p] = fmaxf(f.x, 0.f);
        v[2 * p + 1] = fmaxf(f.y, 0.f);
    }
    // ---- layer 3 (no relu) ----
#pragma unroll
    for (int p = 0; p < 8; p++) acc[p] = sbp[16 + p];
#pragma unroll
    for (int jj = 0; jj < 16; jj++) {
        unsigned long long bv = pk2(v[jj], v[jj]);
#pragma unroll
        for (int p = 0; p < 8; p++) acc[p] = fma2(sW3p[jj * 8 + p], bv, acc[p]);
    }
#pragma unroll
    for (int p = 0; p < 8; p++) {
        float2 f = upk2(acc[p]);
        v[2 * p] = f.x;
        v[2 * p + 1] = f.y;
    }

    float4* fp = (float4*)(g_E3f + (size_t)g * 16);
    fp[0] = make_float4(v[0], v[1], v[2], v[3]);
    fp[1] = make_float4(v[4], v[5], v[6], v[7]);
    fp[2] = make_float4(v[8], v[9], v[10], v[11]);
    fp[3] = make_float4(v[12], v[13], v[14], v[15]);

    uint4 hv[2];
    unsigned* hw = (unsigned*)hv;
#pragma unroll
    for (int q = 0; q < 8; q++) {
        __half2 p = __floats2half2_rn(v[2 * q], v[2 * q + 1]);
        hw[q] = *(unsigned*)&p;
    }
    g_E3h[(size_t)g * 2 + 0] = hv[0];
    g_E3h[(size_t)g * 2 + 1] = hv[1];
}

// ---------------------------------------------------------------------------
// Kernel 2: UW[g,j,k] = sum_l MW[j,k,l]*E3[g,l], fp16 output. (R9 version)
// ---------------------------------------------------------------------------
__global__ void k_uw(int genes) {
    __shared__ float sv[GBLK * 17];
    int t = threadIdx.x;
    int base = blockIdx.x * GBLK;

    {
        int fidx = base * 4 + t;
        int gl = t >> 2, q = t & 3;
        float4 v = make_float4(0.f, 0.f, 0.f, 0.f);
        if (fidx < genes * 4) v = ((const float4*)g_E3f)[fidx];
        sv[gl * 17 + q * 4 + 0] = v.x;
        sv[gl * 17 + q * 4 + 1] = v.y;
        sv[gl * 17 + q * 4 + 2] = v.z;
        sv[gl * 17 + q * 4 + 3] = v.w;
    }

    int j = t & 15;
    int c = (t >> 4) & 3;
    int sg = t >> 6;

    float mw[64];
    {
        const float4* mp = (const float4*)(g_MW + j * 256 + c * 64);
#pragma unroll
        for (int q = 0; q < 16; q++) {
            float4 m4 = mp[q];
            mw[q*4+0]=m4.x; mw[q*4+1]=m4.y; mw[q*4+2]=m4.z; mw[q*4+3]=m4.w;
        }
    }
    __syncthreads();

    uint2* outp = (uint2*)g_UWh;
#pragma unroll
    for (int gi = 0; gi < 16; gi++) {
        int gl = gi * 4 + sg;
        int g = base + gl;
        float u0 = 0.f, u1 = 0.f, u2 = 0.f, u3 = 0.f;
#pragma unroll
        for (int l = 0; l < 16; l++) {
            float ev = sv[gl * 17 + l];
            u0 = fmaf(mw[0  + l], ev, u0);
            u1 = fmaf(mw[16 + l], ev, u1);
            u2 = fmaf(mw[32 + l], ev, u2);
            u3 = fmaf(mw[48 + l], ev, u3);
        }
        if (g < genes) {
            __half2 h01 = __floats2half2_rn(u0, u1);
            __half2 h23 = __floats2half2_rn(u2, u3);
            uint2 v;
            v.x = *(unsigned*)&h01;
            v.y = *(unsigned*)&h23;
            outp[(size_t)g * 64 + (c >> 1) * 32 + j * 2 + (c & 1)] = v;
        }
    }
}

// ---------------------------------------------------------------------------
// Kernel 3: main. 4 rows per 16-lane group (64 rows/block). (R9 version)
// ---------------------------------------------------------------------------
__global__ void k_main(const int* __restrict__ x, const float* __restrict__ phenos,
                       const float* __restrict__ Wc2, const float* __restrict__ bc2,
                       float* __restrict__ out) {
    int t = threadIdx.x;
    int j = t & 15;
    int grp = t >> 4;
    int rbase = blockIdx.x * 64 + grp;

    float bbj = g_bb[j];
    float wc = Wc2[j];
    float acc[4];

#pragma unroll
    for (int r = 0; r < 4; r++) {
        int row = rbase + 16 * r;
        int2 xi = ((const int2*)x)[row];
        const uint4* E = g_E3h + (size_t)xi.x * 2;
        uint4 e0 = E[0], e1 = E[1];
        const uint4* U = g_UWh + (size_t)xi.y * 32;
        uint4 ua = U[j], ub = U[16 + j];

        float z = bbj;
        unsigned ue[8] = {e0.x, e0.y, e0.z, e0.w, e1.x, e1.y, e1.z, e1.w};
        unsigned uu[8] = {ua.x, ua.y, ua.z, ua.w, ub.x, ub.y, ub.z, ub.w};
#pragma unroll
        for (int q = 0; q < 8; q++) {
            float2 a = __half22float2(*(__half2*)&ue[q]);
            float2 u = __half22float2(*(__half2*)&uu[q]);
            z = fmaf(a.x, u.x, z);
            z = fmaf(a.y, u.y, z);
        }
        acc[r] = fmaxf(z, 0.f) * wc;
    }

#pragma unroll
    for (int m = 8; m >= 1; m >>= 1) {
#pragma unroll
        for (int r = 0; r < 4; r++)
            acc[r] += __shfl_xor_sync(0xffffffffu, acc[r], m);
    }

    if (j == 0) {
        float bc = bc2[0];
#pragma unroll
        for (int r = 0; r < 4; r++) {
            int row = rbase + 16 * r;
            float2 p = ((const float2*)phenos)[row];
            out[row] = acc[r] + bc + p.x + p.y;
        }
    }
}

// ---------------------------------------------------------------------------
extern "C" void kernel_launch(void* const* d_in, const int* in_sizes, int n_in,
                              void* d_out, int out_size) {
    const int*   x      = (const int*)d_in[0];
    const float* phenos = (const float*)d_in[1];
    const float* emb    = (const float*)d_in[2];
    const float* W1 = (const float*)d_in[3],  *b1 = (const float*)d_in[4];
    const float* W2 = (const float*)d_in[5],  *b2 = (const float*)d_in[6];
    const float* W3 = (const float*)d_in[7],  *b3 = (const float*)d_in[8];
    const float* BW = (const float*)d_in[9],  *BD = (const float*)d_in[10];
    const float* Boff = (const float*)d_in[11];
    const float* Wc1 = (const float*)d_in[12], *bc1 = (const float*)d_in[13];
    const float* Wc2 = (const float*)d_in[14], *bc2 = (const float*)d_in[15];
    float* out = (float*)d_out;

    int rows  = in_sizes[0] / 2;     // 262144
    int genes = in_sizes[2] / D;     // 20000

    int eblocks = (genes + 255) / 256;                // 79
    k_pre<<<16 + eblocks, 256>>>(BW, BD, Wc1, bc1, Boff, emb,
                                 W1, b1, W2, b2, W3, b3, genes);
    k_uw<<<(genes + GBLK - 1) / GBLK, 256>>>(genes);
    k_main<<<rows / 64, 256>>>(x, phenos, Wc2, bc2, out);
}